// round 1
// baseline (speedup 1.0000x reference)
#include <cuda_runtime.h>
#include <math.h>

#define HW     16384
#define IMG    128
#define DD     72
#define DKV    67
#define TS     8
#define RAD    5
#define KW     11
#define HALO   18      // TS + KW - 1
#define NNB    121
#define SSTRIDE 133    // gcd(133 mod 32 = 5, 32) = 1 -> conflict-free column walks
#define SCALE  0.11785113019775793f  // 1/sqrt(72)

// scratch: xq(72) xkv(67) q(72) kv(72) qh(72) kp(72) vp(72) o1(72) gp(72)
__device__ float g_scratch[HW * (72 * 8 + 67)];

__device__ __forceinline__ float gelu_exact(float x) {
    return 0.5f * x * (1.0f + erff(x * 0.70710678118654752f));
}

// ---------------------------------------------------------------------------
// concat inputs: xq = [gamma0+gammat | pi] (72), xkv = [gamma0+gammat | f] (67)
// ---------------------------------------------------------------------------
__global__ void concat_kernel(const float* __restrict__ f,
                              const float* __restrict__ g0,
                              const float* __restrict__ gt,
                              const float* __restrict__ pi,
                              float* __restrict__ xq,
                              float* __restrict__ xkv) {
    int i = blockIdx.x * 256 + threadIdx.x;
    const int nq = HW * 72;
    if (i < nq) {
        int pix = i / 72, c = i - pix * 72;
        xq[i] = (c < 64) ? (g0[pix * 64 + c] + gt[pix * 64 + c])
                         : pi[pix * 8 + (c - 64)];
    } else {
        int k = i - nq;
        if (k < HW * 67) {
            int pix = k / 67, c = k - pix * 67;
            xkv[k] = (c < 64) ? (g0[pix * 64 + c] + gt[pix * 64 + c])
                              : f[pix * 3 + (c - 64)];
        }
    }
}

// ---------------------------------------------------------------------------
// Y[N,72] = act(X[N,DIN] @ W[DIN,72] + b)
// tile: 64 pixels x 72 outs, 384 threads, thread = 4 px x 3 outs
// ---------------------------------------------------------------------------
template <int DIN, int ACT>
__global__ __launch_bounds__(384) void proj_kernel(const float* __restrict__ X,
                                                   const float* __restrict__ W,
                                                   const float* __restrict__ B,
                                                   float* __restrict__ Y) {
    __shared__ float Xs[DIN * 64];
    __shared__ float Ws[DIN * 72];
    __shared__ float bs[72];
    const int tid = threadIdx.x;
    const int pix0 = blockIdx.x * 64;

    for (int i = tid; i < DIN * 64; i += 384) {
        int p = i / DIN, k = i - p * DIN;
        Xs[k * 64 + p] = X[(pix0 + p) * DIN + k];
    }
    for (int i = tid; i < DIN * 72; i += 384) Ws[i] = W[i];
    if (tid < 72) bs[tid] = B[tid];
    __syncthreads();

    const int og = tid % 24;       // 24 * 3 = 72 outs
    const int pg = tid / 24;       // 16 * 4 = 64 px
    const int xb = pg * 4, ob = og * 3;

    float acc[4][3];
#pragma unroll
    for (int i = 0; i < 4; i++)
#pragma unroll
        for (int j = 0; j < 3; j++) acc[i][j] = 0.0f;

    for (int k = 0; k < DIN; k++) {
        float x0 = Xs[k * 64 + xb + 0];
        float x1 = Xs[k * 64 + xb + 1];
        float x2 = Xs[k * 64 + xb + 2];
        float x3 = Xs[k * 64 + xb + 3];
        float w0 = Ws[k * 72 + ob + 0];
        float w1 = Ws[k * 72 + ob + 1];
        float w2 = Ws[k * 72 + ob + 2];
        acc[0][0] += x0 * w0; acc[0][1] += x0 * w1; acc[0][2] += x0 * w2;
        acc[1][0] += x1 * w0; acc[1][1] += x1 * w1; acc[1][2] += x1 * w2;
        acc[2][0] += x2 * w0; acc[2][1] += x2 * w1; acc[2][2] += x2 * w2;
        acc[3][0] += x3 * w0; acc[3][1] += x3 * w1; acc[3][2] += x3 * w2;
    }
#pragma unroll
    for (int i = 0; i < 4; i++)
#pragma unroll
        for (int j = 0; j < 3; j++) {
            float v = acc[i][j] + bs[ob + j];
            if (ACT) v = gelu_exact(v);
            Y[(pix0 + xb + i) * 72 + ob + j] = v;
        }
}

// ---------------------------------------------------------------------------
// Attention: 8x8 pixel tile per block, 18x18 halo of K and V in smem.
// ---------------------------------------------------------------------------
__global__ __launch_bounds__(256) void attn_kernel(const float* __restrict__ Q,
                                                   const float* __restrict__ Kp,
                                                   const float* __restrict__ Vp,
                                                   float* __restrict__ O) {
    extern __shared__ float sm[];
    float* Ks  = sm;                          // 324*72
    float* Vs  = Ks + HALO * HALO * 72;       // 324*72
    float* S   = Vs + HALO * HALO * 72;       // 64*SSTRIDE
    float* red = S + 64 * SSTRIDE;            // 64

    const int tid = threadIdx.x;
    const int tx = blockIdx.x, ty = blockIdx.y;
    const int ox = tx * TS - RAD, oy = ty * TS - RAD;

    // halo load (zero-fill out of bounds)
    float4* Ks4 = (float4*)Ks;
    float4* Vs4 = (float4*)Vs;
    for (int i = tid; i < HALO * HALO * 18; i += 256) {
        int cell = i / 18, j = i - cell * 18;
        int hy = cell / HALO, hx = cell - hy * HALO;
        int gy = oy + hy, gx = ox + hx;
        float4 kv4 = make_float4(0.f, 0.f, 0.f, 0.f);
        float4 vv4 = kv4;
        if ((unsigned)gy < IMG && (unsigned)gx < IMG) {
            int base = (gy * IMG + gx) * 18;
            kv4 = __ldg((const float4*)Kp + base + j);
            vv4 = __ldg((const float4*)Vp + base + j);
        }
        Ks4[i] = kv4;
        Vs4[i] = vv4;
    }
    __syncthreads();

    // ---- phase A: scores ----
    {
        const int p = tid >> 2, sub = tid & 3;
        const int py = p >> 3, px = p & 7;
        const int gy = ty * TS + py, gx = tx * TS + px;
        float4 q4[18];
        const float4* qr = (const float4*)(Q + (gy * IMG + gx) * 72);
#pragma unroll
        for (int j = 0; j < 18; j++) q4[j] = __ldg(qr + j);

        for (int n = sub; n < NNB; n += 4) {
            int qy = n / 11;
            int qxo = n - qy * 11;
            int ny = gy + qy - RAD, nx = gx + qxo - RAD;
            float s = -INFINITY;
            if ((unsigned)ny < IMG && (unsigned)nx < IMG) {
                const float4* kr = (const float4*)Ks + ((py + qy) * HALO + (px + qxo)) * 18;
                float a0 = 0.f, a1 = 0.f, a2 = 0.f, a3 = 0.f;
#pragma unroll
                for (int j = 0; j < 18; j += 2) {
                    float4 k0 = kr[j];
                    float4 k1 = kr[j + 1];
                    a0 += q4[j].x * k0.x + q4[j].y * k0.y;
                    a1 += q4[j].z * k0.z + q4[j].w * k0.w;
                    a2 += q4[j + 1].x * k1.x + q4[j + 1].y * k1.y;
                    a3 += q4[j + 1].z * k1.z + q4[j + 1].w * k1.w;
                }
                s = (a0 + a1 + a2 + a3) * SCALE;
            }
            S[p * SSTRIDE + n] = s;
        }
    }
    __syncthreads();

    // ---- softmax (unnormalized exp; reciprocal sum in red[]) ----
    if (tid < 64) {
        float* row = S + tid * SSTRIDE;
        float m = -INFINITY;
        for (int n = 0; n < NNB; n++) m = fmaxf(m, row[n]);
        float sum = 0.f;
        for (int n = 0; n < NNB; n++) {
            float e = __expf(row[n] - m);
            row[n] = e;
            sum += e;
        }
        red[tid] = 1.0f / sum;
    }
    __syncthreads();

    // ---- phase B: attn @ V ----
    for (int u = tid; u < 64 * 18; u += 256) {
        int p = u / 18, j = u - p * 18;
        int py = p >> 3, px = p & 7;
        const float* arow = S + p * SSTRIDE;
        float4 acc = make_float4(0.f, 0.f, 0.f, 0.f);
#pragma unroll 1
        for (int dy = 0; dy < KW; dy++) {
            const float4* vbase = (const float4*)Vs + (((py + dy) * HALO) + px) * 18 + j;
            const float* ar = arow + dy * KW;
#pragma unroll
            for (int dx = 0; dx < KW; dx++) {
                float a = ar[dx];
                float4 v = vbase[dx * 18];
                acc.x += a * v.x;
                acc.y += a * v.y;
                acc.z += a * v.z;
                acc.w += a * v.w;
            }
        }
        float r = red[p];
        acc.x *= r; acc.y *= r; acc.z *= r; acc.w *= r;
        int gy = ty * TS + py, gx = tx * TS + px;
        ((float4*)O)[(gy * IMG + gx) * 18 + j] = acc;
    }
}

// ---------------------------------------------------------------------------
// heads: g = [sigmoid(gr[:4]) | softmax(gr[4:7])], p = softmax(pi @ w_p + b_p)
// ---------------------------------------------------------------------------
__global__ __launch_bounds__(256) void head_kernel(const float* __restrict__ gp,
                                                   const float* __restrict__ WG,
                                                   const float* __restrict__ BG,
                                                   const float* __restrict__ WP,
                                                   const float* __restrict__ BP,
                                                   float* __restrict__ out) {
    __shared__ float wg[64 * 7];
    __shared__ float bg[7];
    __shared__ float wp[24];
    __shared__ float bp[3];
    const int tid = threadIdx.x;
    for (int i = tid; i < 448; i += 256) wg[i] = WG[i];
    if (tid < 7)  bg[tid] = BG[tid];
    if (tid < 24) wp[tid] = WP[tid];
    if (tid < 3)  bp[tid] = BP[tid];
    __syncthreads();

    int pix = blockIdx.x * 256 + tid;
    const float* row = gp + pix * 72;

    float gr[7];
#pragma unroll
    for (int j = 0; j < 7; j++) gr[j] = bg[j];
    for (int c = 0; c < 64; c++) {
        float x = row[c];
#pragma unroll
        for (int j = 0; j < 7; j++) gr[j] += x * wg[c * 7 + j];
    }
    float go[7];
#pragma unroll
    for (int j = 0; j < 4; j++) go[j] = 1.0f / (1.0f + __expf(-gr[j]));
    {
        float m = fmaxf(gr[4], fmaxf(gr[5], gr[6]));
        float e0 = __expf(gr[4] - m), e1 = __expf(gr[5] - m), e2 = __expf(gr[6] - m);
        float rs = 1.0f / (e0 + e1 + e2);
        go[4] = e0 * rs; go[5] = e1 * rs; go[6] = e2 * rs;
    }
#pragma unroll
    for (int j = 0; j < 7; j++) out[pix * 7 + j] = go[j];

    float pr[3];
#pragma unroll
    for (int j = 0; j < 3; j++) pr[j] = bp[j];
    for (int c = 0; c < 8; c++) {
        float x = row[64 + c];
#pragma unroll
        for (int j = 0; j < 3; j++) pr[j] += x * wp[c * 3 + j];
    }
    {
        float m = fmaxf(pr[0], fmaxf(pr[1], pr[2]));
        float e0 = __expf(pr[0] - m), e1 = __expf(pr[1] - m), e2 = __expf(pr[2] - m);
        float rs = 1.0f / (e0 + e1 + e2);
        out[HW * 7 + pix * 3 + 0] = e0 * rs;
        out[HW * 7 + pix * 3 + 1] = e1 * rs;
        out[HW * 7 + pix * 3 + 2] = e2 * rs;
    }
}

// split gp -> gamma_next (out+HW*10), pi_next (out+HW*74)
__global__ void split_kernel(const float* __restrict__ gp, float* __restrict__ out) {
    int i = blockIdx.x * 256 + threadIdx.x;
    if (i < HW * 72) {
        int pix = i / 72, c = i - pix * 72;
        float v = gp[i];
        if (c < 64) out[HW * 10 + pix * 64 + c] = v;
        else        out[HW * 74 + pix * 8 + (c - 64)] = v;
    }
}

// ---------------------------------------------------------------------------
extern "C" void kernel_launch(void* const* d_in, const int* in_sizes, int n_in,
                              void* d_out, int out_size) {
    const float* f_t     = (const float*)d_in[0];
    const float* gamma_0 = (const float*)d_in[1];
    const float* gamma_t = (const float*)d_in[2];
    const float* pi_t    = (const float*)d_in[3];
    const float* w_mlp1  = (const float*)d_in[4];
    const float* b_mlp1  = (const float*)d_in[5];
    const float* w_mlp2  = (const float*)d_in[6];
    const float* b_mlp2  = (const float*)d_in[7];
    const float* wq1     = (const float*)d_in[8];
    const float* bq1     = (const float*)d_in[9];
    const float* wk1     = (const float*)d_in[10];
    const float* bk1     = (const float*)d_in[11];
    const float* wv1     = (const float*)d_in[12];
    const float* bv1     = (const float*)d_in[13];
    const float* wq2     = (const float*)d_in[14];
    const float* bq2     = (const float*)d_in[15];
    const float* wk2     = (const float*)d_in[16];
    const float* bk2     = (const float*)d_in[17];
    const float* wv2     = (const float*)d_in[18];
    const float* bv2     = (const float*)d_in[19];
    const float* w_g     = (const float*)d_in[20];
    const float* b_g     = (const float*)d_in[21];
    const float* w_p     = (const float*)d_in[22];
    const float* b_p     = (const float*)d_in[23];
    float* out = (float*)d_out;

    float* base = nullptr;
    cudaGetSymbolAddress((void**)&base, g_scratch);
    float* xq  = base;
    float* xkv = xq  + HW * 72;
    float* q   = xkv + HW * 67;
    float* kv  = q   + HW * 72;
    float* qh  = kv  + HW * 72;
    float* kp  = qh  + HW * 72;
    float* vp  = kp  + HW * 72;
    float* o1  = vp  + HW * 72;
    float* gp  = o1  + HW * 72;

    const int smem_bytes = (HALO * HALO * 72 * 2 + 64 * SSTRIDE + 64) * (int)sizeof(float);
    cudaFuncSetAttribute(attn_kernel, cudaFuncAttributeMaxDynamicSharedMemorySize, smem_bytes);

    concat_kernel<<<(HW * 139 + 255) / 256, 256>>>(f_t, gamma_0, gamma_t, pi_t, xq, xkv);
    proj_kernel<72, 1><<<256, 384>>>(xq,  w_mlp1, b_mlp1, q);
    proj_kernel<67, 1><<<256, 384>>>(xkv, w_mlp2, b_mlp2, kv);

    proj_kernel<72, 0><<<256, 384>>>(q,  wq1, bq1, qh);
    proj_kernel<72, 0><<<256, 384>>>(kv, wk1, bk1, kp);
    proj_kernel<72, 0><<<256, 384>>>(kv, wv1, bv1, vp);
    attn_kernel<<<dim3(16, 16), 256, smem_bytes>>>(qh, kp, vp, o1);

    proj_kernel<72, 0><<<256, 384>>>(q,  wq2, bq2, qh);
    proj_kernel<72, 0><<<256, 384>>>(o1, wk2, bk2, kp);
    proj_kernel<72, 0><<<256, 384>>>(o1, wv2, bv2, vp);
    attn_kernel<<<dim3(16, 16), 256, smem_bytes>>>(qh, kp, vp, gp);

    head_kernel<<<HW / 256, 256>>>(gp, w_g, b_g, w_p, b_p, out);
    split_kernel<<<(HW * 72 + 255) / 256, 256>>>(gp, out);
}

// round 2
// speedup vs baseline: 1.5047x; 1.5047x over previous
#include <cuda_runtime.h>
#include <math.h>

#define HW     16384
#define IMG    128
#define TS     8
#define RAD    5
#define KW     11
#define HALO   18      // TS + KW - 1
#define NNB    121
#define SSTR   124
#define KSTR   325     // halo cells 324, padded; 325%32=5 coprime -> conflict-free
#define SCALE  0.11785113019775793f  // 1/sqrt(72)

// scratch: q, kv, qh1, qh2, kp, vp, o1, gp  (8 x HW x 72) -- keep old size
__device__ float g_scratch[HW * (72 * 8 + 67)];

__device__ __forceinline__ float gelu_exact(float x) {
    return 0.5f * x * (1.0f + erff(x * 0.70710678118654752f));
}

// ---------------------------------------------------------------------------
// MLP projection with fused concat:
//   X[p] = [gamma0[p]+gammat[p] (64) | tail[p] (TAIL)],  Y = gelu(X @ W + b)
// 64 px per block, 288 threads = 16 pxgroups(4) x 18 outgroups(4)
// ---------------------------------------------------------------------------
template <int TAIL>
__global__ __launch_bounds__(288) void mlp_kernel(const float* __restrict__ g0,
                                                  const float* __restrict__ gt,
                                                  const float* __restrict__ tail,
                                                  const float* __restrict__ W,
                                                  const float* __restrict__ B,
                                                  float* __restrict__ Y) {
    constexpr int DIN = 64 + TAIL;
    __shared__ float Xs[64 * DIN];
    __shared__ float Ws[DIN * 72];
    __shared__ float bs[72];
    const int tid = threadIdx.x;
    const int pix0 = blockIdx.x * 64;

    for (int i = tid; i < 64 * 64; i += 288) {
        int p = i >> 6, c = i & 63;
        Xs[p * DIN + c] = g0[(pix0 + p) * 64 + c] + gt[(pix0 + p) * 64 + c];
    }
    for (int i = tid; i < 64 * TAIL; i += 288) {
        int p = i / TAIL, c = i - p * TAIL;
        Xs[p * DIN + 64 + c] = tail[(pix0 + p) * TAIL + c];
    }
    for (int i = tid; i < DIN * 18; i += 288)
        ((float4*)Ws)[i] = ((const float4*)W)[i];
    if (tid < 72) bs[tid] = B[tid];
    __syncthreads();

    const int og = tid % 18, pg = tid / 18;
    const int ob = og * 4, xb = pg * 4;

    float acc[4][4];
#pragma unroll
    for (int i = 0; i < 4; i++)
#pragma unroll
        for (int j = 0; j < 4; j++) acc[i][j] = 0.0f;

    for (int k = 0; k < DIN; k++) {
        float x0 = Xs[(xb + 0) * DIN + k];
        float x1 = Xs[(xb + 1) * DIN + k];
        float x2 = Xs[(xb + 2) * DIN + k];
        float x3 = Xs[(xb + 3) * DIN + k];
        float4 w = *(const float4*)&Ws[k * 72 + ob];
        acc[0][0] += x0 * w.x; acc[0][1] += x0 * w.y; acc[0][2] += x0 * w.z; acc[0][3] += x0 * w.w;
        acc[1][0] += x1 * w.x; acc[1][1] += x1 * w.y; acc[1][2] += x1 * w.z; acc[1][3] += x1 * w.w;
        acc[2][0] += x2 * w.x; acc[2][1] += x2 * w.y; acc[2][2] += x2 * w.z; acc[2][3] += x2 * w.w;
        acc[3][0] += x3 * w.x; acc[3][1] += x3 * w.y; acc[3][2] += x3 * w.z; acc[3][3] += x3 * w.w;
    }
#pragma unroll
    for (int i = 0; i < 4; i++) {
        float4 r;
        r.x = gelu_exact(acc[i][0] + bs[ob + 0]);
        r.y = gelu_exact(acc[i][1] + bs[ob + 1]);
        r.z = gelu_exact(acc[i][2] + bs[ob + 2]);
        r.w = gelu_exact(acc[i][3] + bs[ob + 3]);
        *(float4*)&Y[(pix0 + xb + i) * 72 + ob] = r;
    }
}

// ---------------------------------------------------------------------------
// Dual projection: Y1 = X @ W1 + b1, Y2 = X @ W2 + b2  (DIN=72, no activation)
// Shares X smem loads between both outputs. 64 px, 288 threads, 4px x 4outs x2.
// ---------------------------------------------------------------------------
__global__ __launch_bounds__(288) void proj_dual_kernel(const float* __restrict__ X,
                                                        const float* __restrict__ W1,
                                                        const float* __restrict__ B1,
                                                        float* __restrict__ Y1,
                                                        const float* __restrict__ W2,
                                                        const float* __restrict__ B2,
                                                        float* __restrict__ Y2) {
    extern __shared__ float dsm[];
    float* Xs  = dsm;              // 64*72
    float* Ws1 = Xs + 64 * 72;     // 72*72
    float* Ws2 = Ws1 + 72 * 72;    // 72*72
    float* bs1 = Ws2 + 72 * 72;    // 72
    float* bs2 = bs1 + 72;         // 72

    const int tid = threadIdx.x;
    const int pix0 = blockIdx.x * 64;

    for (int i = tid; i < 64 * 18; i += 288)
        ((float4*)Xs)[i] = ((const float4*)(X + pix0 * 72))[i];
    for (int i = tid; i < 72 * 18; i += 288) {
        ((float4*)Ws1)[i] = ((const float4*)W1)[i];
        ((float4*)Ws2)[i] = ((const float4*)W2)[i];
    }
    if (tid < 72) { bs1[tid] = B1[tid]; bs2[tid] = B2[tid]; }
    __syncthreads();

    const int og = tid % 18, pg = tid / 18;
    const int ob = og * 4, xb = pg * 4;

    float a1[4][4], a2[4][4];
#pragma unroll
    for (int i = 0; i < 4; i++)
#pragma unroll
        for (int j = 0; j < 4; j++) { a1[i][j] = 0.0f; a2[i][j] = 0.0f; }

    for (int k = 0; k < 72; k++) {
        float x0 = Xs[(xb + 0) * 72 + k];
        float x1 = Xs[(xb + 1) * 72 + k];
        float x2 = Xs[(xb + 2) * 72 + k];
        float x3 = Xs[(xb + 3) * 72 + k];
        float4 w1 = *(const float4*)&Ws1[k * 72 + ob];
        float4 w2 = *(const float4*)&Ws2[k * 72 + ob];
        a1[0][0] += x0 * w1.x; a1[0][1] += x0 * w1.y; a1[0][2] += x0 * w1.z; a1[0][3] += x0 * w1.w;
        a1[1][0] += x1 * w1.x; a1[1][1] += x1 * w1.y; a1[1][2] += x1 * w1.z; a1[1][3] += x1 * w1.w;
        a1[2][0] += x2 * w1.x; a1[2][1] += x2 * w1.y; a1[2][2] += x2 * w1.z; a1[2][3] += x2 * w1.w;
        a1[3][0] += x3 * w1.x; a1[3][1] += x3 * w1.y; a1[3][2] += x3 * w1.z; a1[3][3] += x3 * w1.w;
        a2[0][0] += x0 * w2.x; a2[0][1] += x0 * w2.y; a2[0][2] += x0 * w2.z; a2[0][3] += x0 * w2.w;
        a2[1][0] += x1 * w2.x; a2[1][1] += x1 * w2.y; a2[1][2] += x1 * w2.z; a2[1][3] += x1 * w2.w;
        a2[2][0] += x2 * w2.x; a2[2][1] += x2 * w2.y; a2[2][2] += x2 * w2.z; a2[2][3] += x2 * w2.w;
        a2[3][0] += x3 * w2.x; a2[3][1] += x3 * w2.y; a2[3][2] += x3 * w2.z; a2[3][3] += x3 * w2.w;
    }
#pragma unroll
    for (int i = 0; i < 4; i++) {
        float4 r1, r2;
        r1.x = a1[i][0] + bs1[ob + 0]; r1.y = a1[i][1] + bs1[ob + 1];
        r1.z = a1[i][2] + bs1[ob + 2]; r1.w = a1[i][3] + bs1[ob + 3];
        r2.x = a2[i][0] + bs2[ob + 0]; r2.y = a2[i][1] + bs2[ob + 1];
        r2.z = a2[i][2] + bs2[ob + 2]; r2.w = a2[i][3] + bs2[ob + 3];
        *(float4*)&Y1[(pix0 + xb + i) * 72 + ob] = r1;
        *(float4*)&Y2[(pix0 + xb + i) * 72 + ob] = r2;
    }
}

// ---------------------------------------------------------------------------
// Attention v2: 8x8 tile, 512 threads.
// K halo channel-major (stride 325, conflict-free scalar loads in phase A),
// V halo cell-major float4 (contiguous in phase B). Warp-local softmax.
// ---------------------------------------------------------------------------
__global__ __launch_bounds__(512) void attn_kernel(const float* __restrict__ Q,
                                                   const float* __restrict__ Kp,
                                                   const float* __restrict__ Vp,
                                                   float* __restrict__ O) {
    extern __shared__ float sm[];
    float* Ks  = sm;                       // 72 * KSTR channel-major
    float* Vs  = Ks + 72 * KSTR;           // 324 * 72 cell-major
    float* S   = Vs + HALO * HALO * 72;    // 64 * SSTR
    float* red = S + 64 * SSTR;            // 64

    const int tid = threadIdx.x;
    const int tx = blockIdx.x, ty = blockIdx.y;
    const int ox = tx * TS - RAD, oy = ty * TS - RAD;

    // halo load
    float4* Vs4 = (float4*)Vs;
    for (int i = tid; i < HALO * HALO * 18; i += 512) {
        int cell = i / 18, j = i - cell * 18;
        int hy = cell / HALO, hx = cell - hy * HALO;
        int gy = oy + hy, gx = ox + hx;
        float4 kv = make_float4(0.f, 0.f, 0.f, 0.f);
        float4 vv = kv;
        if ((unsigned)gy < IMG && (unsigned)gx < IMG) {
            int base = (gy * IMG + gx) * 18;
            kv = __ldg((const float4*)Kp + base + j);
            vv = __ldg((const float4*)Vp + base + j);
        }
        Vs4[i] = vv;
        Ks[(4 * j + 0) * KSTR + cell] = kv.x;
        Ks[(4 * j + 1) * KSTR + cell] = kv.y;
        Ks[(4 * j + 2) * KSTR + cell] = kv.z;
        Ks[(4 * j + 3) * KSTR + cell] = kv.w;
    }
    __syncthreads();

    const int p = tid >> 3, sub = tid & 7;
    const int py = p >> 3, px = p & 7;
    const int gy = ty * TS + py, gx = tx * TS + px;

    // ---- phase A: scores ----
    {
        float q[72];
        const float4* qr = (const float4*)(Q + (gy * IMG + gx) * 72);
#pragma unroll
        for (int jj = 0; jj < 18; jj++) {
            float4 t = __ldg(qr + jj);
            q[4 * jj + 0] = t.x; q[4 * jj + 1] = t.y;
            q[4 * jj + 2] = t.z; q[4 * jj + 3] = t.w;
        }
        for (int n = sub; n < NNB; n += 8) {
            int qy = n / 11;
            int qx = n - qy * 11;
            int ny = gy + qy - RAD, nx = gx + qx - RAD;
            float s = -INFINITY;
            if ((unsigned)ny < IMG && (unsigned)nx < IMG) {
                const float* kc = Ks + (py + qy) * HALO + (px + qx);
                float a0 = 0.f, a1 = 0.f, a2 = 0.f, a3 = 0.f;
#pragma unroll
                for (int j = 0; j < 72; j += 4) {
                    a0 += q[j + 0] * kc[(j + 0) * KSTR];
                    a1 += q[j + 1] * kc[(j + 1) * KSTR];
                    a2 += q[j + 2] * kc[(j + 2) * KSTR];
                    a3 += q[j + 3] * kc[(j + 3) * KSTR];
                }
                s = (a0 + a1 + a2 + a3) * SCALE;
            }
            S[p * SSTR + n] = s;
        }
    }
    __syncwarp();

    // ---- softmax: 8-lane cooperative (same lanes wrote this row) ----
    {
        float* row = S + p * SSTR;
        float m = -INFINITY;
        for (int n = sub; n < NNB; n += 8) m = fmaxf(m, row[n]);
        m = fmaxf(m, __shfl_xor_sync(0xffffffffu, m, 1));
        m = fmaxf(m, __shfl_xor_sync(0xffffffffu, m, 2));
        m = fmaxf(m, __shfl_xor_sync(0xffffffffu, m, 4));
        float sum = 0.f;
        for (int n = sub; n < NNB; n += 8) {
            float e = __expf(row[n] - m);
            row[n] = e;
            sum += e;
        }
        sum += __shfl_xor_sync(0xffffffffu, sum, 1);
        sum += __shfl_xor_sync(0xffffffffu, sum, 2);
        sum += __shfl_xor_sync(0xffffffffu, sum, 4);
        if (sub == 0) red[p] = 1.0f / sum;
    }
    __syncthreads();

    // ---- phase B: attn @ V ----
    for (int u = tid; u < 64 * 18; u += 512) {
        int pp = u / 18, j = u - pp * 18;
        int ppy = pp >> 3, ppx = pp & 7;
        const float* arow = S + pp * SSTR;
        float4 acc = make_float4(0.f, 0.f, 0.f, 0.f);
#pragma unroll 1
        for (int dy = 0; dy < KW; dy++) {
            const float4* vb = (const float4*)Vs + (((ppy + dy) * HALO) + ppx) * 18 + j;
            const float* ar = arow + dy * KW;
#pragma unroll
            for (int dx = 0; dx < KW; dx++) {
                float a = ar[dx];
                float4 v = vb[dx * 18];
                acc.x += a * v.x;
                acc.y += a * v.y;
                acc.z += a * v.z;
                acc.w += a * v.w;
            }
        }
        float r = red[pp];
        acc.x *= r; acc.y *= r; acc.z *= r; acc.w *= r;
        int ogy = ty * TS + ppy, ogx = tx * TS + ppx;
        ((float4*)O)[(ogy * IMG + ogx) * 18 + j] = acc;
    }
}

// ---------------------------------------------------------------------------
// heads
// ---------------------------------------------------------------------------
__global__ __launch_bounds__(256) void head_kernel(const float* __restrict__ gp,
                                                   const float* __restrict__ WG,
                                                   const float* __restrict__ BG,
                                                   const float* __restrict__ WP,
                                                   const float* __restrict__ BP,
                                                   float* __restrict__ out) {
    __shared__ float wg[64 * 7];
    __shared__ float bg[7];
    __shared__ float wp[24];
    __shared__ float bp[3];
    const int tid = threadIdx.x;
    for (int i = tid; i < 448; i += 256) wg[i] = WG[i];
    if (tid < 7)  bg[tid] = BG[tid];
    if (tid < 24) wp[tid] = WP[tid];
    if (tid < 3)  bp[tid] = BP[tid];
    __syncthreads();

    int pix = blockIdx.x * 256 + tid;
    const float* row = gp + pix * 72;

    float gr[7];
#pragma unroll
    for (int j = 0; j < 7; j++) gr[j] = bg[j];
    for (int c = 0; c < 64; c++) {
        float x = row[c];
#pragma unroll
        for (int j = 0; j < 7; j++) gr[j] += x * wg[c * 7 + j];
    }
    float go[7];
#pragma unroll
    for (int j = 0; j < 4; j++) go[j] = 1.0f / (1.0f + __expf(-gr[j]));
    {
        float m = fmaxf(gr[4], fmaxf(gr[5], gr[6]));
        float e0 = __expf(gr[4] - m), e1 = __expf(gr[5] - m), e2 = __expf(gr[6] - m);
        float rs = 1.0f / (e0 + e1 + e2);
        go[4] = e0 * rs; go[5] = e1 * rs; go[6] = e2 * rs;
    }
#pragma unroll
    for (int j = 0; j < 7; j++) out[pix * 7 + j] = go[j];

    float pr[3];
#pragma unroll
    for (int j = 0; j < 3; j++) pr[j] = bp[j];
    for (int c = 0; c < 8; c++) {
        float x = row[64 + c];
#pragma unroll
        for (int j = 0; j < 3; j++) pr[j] += x * wp[c * 3 + j];
    }
    {
        float m = fmaxf(pr[0], fmaxf(pr[1], pr[2]));
        float e0 = __expf(pr[0] - m), e1 = __expf(pr[1] - m), e2 = __expf(pr[2] - m);
        float rs = 1.0f / (e0 + e1 + e2);
        out[HW * 7 + pix * 3 + 0] = e0 * rs;
        out[HW * 7 + pix * 3 + 1] = e1 * rs;
        out[HW * 7 + pix * 3 + 2] = e2 * rs;
    }
}

__global__ void split_kernel(const float* __restrict__ gp, float* __restrict__ out) {
    int i = blockIdx.x * 256 + threadIdx.x;
    if (i < HW * 72) {
        int pix = i / 72, c = i - pix * 72;
        float v = gp[i];
        if (c < 64) out[HW * 10 + pix * 64 + c] = v;
        else        out[HW * 74 + pix * 8 + (c - 64)] = v;
    }
}

// ---------------------------------------------------------------------------
extern "C" void kernel_launch(void* const* d_in, const int* in_sizes, int n_in,
                              void* d_out, int out_size) {
    const float* f_t     = (const float*)d_in[0];
    const float* gamma_0 = (const float*)d_in[1];
    const float* gamma_t = (const float*)d_in[2];
    const float* pi_t    = (const float*)d_in[3];
    const float* w_mlp1  = (const float*)d_in[4];
    const float* b_mlp1  = (const float*)d_in[5];
    const float* w_mlp2  = (const float*)d_in[6];
    const float* b_mlp2  = (const float*)d_in[7];
    const float* wq1     = (const float*)d_in[8];
    const float* bq1     = (const float*)d_in[9];
    const float* wk1     = (const float*)d_in[10];
    const float* bk1     = (const float*)d_in[11];
    const float* wv1     = (const float*)d_in[12];
    const float* bv1     = (const float*)d_in[13];
    const float* wq2     = (const float*)d_in[14];
    const float* bq2     = (const float*)d_in[15];
    const float* wk2     = (const float*)d_in[16];
    const float* bk2     = (const float*)d_in[17];
    const float* wv2     = (const float*)d_in[18];
    const float* bv2     = (const float*)d_in[19];
    const float* w_g     = (const float*)d_in[20];
    const float* b_g     = (const float*)d_in[21];
    const float* w_p     = (const float*)d_in[22];
    const float* b_p     = (const float*)d_in[23];
    float* out = (float*)d_out;

    float* base = nullptr;
    cudaGetSymbolAddress((void**)&base, g_scratch);
    float* q   = base;
    float* kv  = q   + HW * 72;
    float* qh1 = kv  + HW * 72;
    float* qh2 = qh1 + HW * 72;
    float* kp  = qh2 + HW * 72;
    float* vp  = kp  + HW * 72;
    float* o1  = vp  + HW * 72;
    float* gp  = o1  + HW * 72;

    const int attn_smem = (72 * KSTR + HALO * HALO * 72 + 64 * SSTR + 64) * (int)sizeof(float);
    cudaFuncSetAttribute(attn_kernel, cudaFuncAttributeMaxDynamicSharedMemorySize, attn_smem);
    const int dual_smem = (64 * 72 + 2 * 72 * 72 + 144) * (int)sizeof(float);
    cudaFuncSetAttribute(proj_dual_kernel, cudaFuncAttributeMaxDynamicSharedMemorySize, dual_smem);

    mlp_kernel<8><<<256, 288>>>(gamma_0, gamma_t, pi_t, w_mlp1, b_mlp1, q);
    mlp_kernel<3><<<256, 288>>>(gamma_0, gamma_t, f_t, w_mlp2, b_mlp2, kv);

    proj_dual_kernel<<<256, 288, dual_smem>>>(q,  wq1, bq1, qh1, wq2, bq2, qh2);
    proj_dual_kernel<<<256, 288, dual_smem>>>(kv, wk1, bk1, kp,  wv1, bv1, vp);
    attn_kernel<<<dim3(16, 16), 512, attn_smem>>>(qh1, kp, vp, o1);

    proj_dual_kernel<<<256, 288, dual_smem>>>(o1, wk2, bk2, kp,  wv2, bv2, vp);
    attn_kernel<<<dim3(16, 16), 512, attn_smem>>>(qh2, kp, vp, gp);

    head_kernel<<<HW / 256, 256>>>(gp, w_g, b_g, w_p, b_p, out);
    split_kernel<<<(HW * 72 + 255) / 256, 256>>>(gp, out);
}